// round 1
// baseline (speedup 1.0000x reference)
#include <cuda_runtime.h>
#include <math.h>

// Problem constants
#define BATCH 16
#define CH    3
#define H     512
#define W     512
#define HW    (H * W)
#define KRAD  5            // kernel_size 11 -> radius 5
#define EPS_LCS  1e-6f
#define EPS_PSNR 1e-8f

// Scratch: three (B,H,W) intermediates after horizontal box sum, plus accumulators.
__device__ float g_sxx[BATCH * HW];
__device__ float g_syy[BATCH * HW];
__device__ float g_sxy[BATCH * HW];
__device__ float g_mse[BATCH];
__device__ float g_cos_sum;

// ---------------------------------------------------------------------------
// Zero accumulators (runs every graph replay)
// ---------------------------------------------------------------------------
__global__ void k_zero() {
    int i = threadIdx.x;
    if (i < BATCH) g_mse[i] = 0.0f;
    if (i == BATCH) g_cos_sum = 0.0f;
}

// ---------------------------------------------------------------------------
// Kernel A: per-row channel products + horizontal 11-tap box sum + MSE partials
// grid = B*H blocks, block = W threads
// ---------------------------------------------------------------------------
__global__ void k_prod_hsum(const float* __restrict__ pred,
                            const float* __restrict__ tgt) {
    int row = blockIdx.x;               // 0..B*H-1
    int b = row >> 9;                   // /512
    int y = row & (H - 1);
    int x = threadIdx.x;                // 0..511

    size_t base = (size_t)b * CH * HW + (size_t)y * W + x;

    float pp = 0.f, tt = 0.f, pt = 0.f, msev = 0.f;
#pragma unroll
    for (int c = 0; c < CH; c++) {
        float p = pred[base + (size_t)c * HW];
        float t = tgt [base + (size_t)c * HW];
        pp += p * p;
        tt += t * t;
        pt += p * t;
        float d = p - t;
        msev += d * d;
    }

    __shared__ float sp[W];
    __shared__ float st[W];
    __shared__ float sx[W];
    sp[x] = pp; st[x] = tt; sx[x] = pt;
    __syncthreads();

    float axx = 0.f, ayy = 0.f, axy = 0.f;
    int lo = x - KRAD; if (lo < 0) lo = 0;
    int hi = x + KRAD; if (hi > W - 1) hi = W - 1;
    for (int j = lo; j <= hi; j++) {
        axx += sp[j];
        ayy += st[j];
        axy += sx[j];
    }

    size_t o = (size_t)b * HW + (size_t)y * W + x;
    g_sxx[o] = axx;
    g_syy[o] = ayy;
    g_sxy[o] = axy;

    // block-reduce msev, one atomic per block into g_mse[b]
    __shared__ float red[W];
    red[x] = msev;
    __syncthreads();
    for (int s = W / 2; s > 0; s >>= 1) {
        if (x < s) red[x] += red[x + s];
        __syncthreads();
    }
    if (x == 0) atomicAdd(&g_mse[b], red[0]);
}

// ---------------------------------------------------------------------------
// Kernel B: vertical 11-tap sliding box sum + cosine + global reduce
// Block handles a 256-wide column strip of one image over a SEG-row y-segment.
// grid = B * (W/256) * NSEG blocks, block = 256 threads
// ---------------------------------------------------------------------------
#define NSEG   8
#define SEG    (H / NSEG)   // 64
#define XSTRIP 256

__global__ void k_vsum_cos() {
    int blk  = blockIdx.x;
    int seg  = blk % NSEG;          blk /= NSEG;
    int xs   = blk % (W / XSTRIP);  blk /= (W / XSTRIP);
    int b    = blk;                 // 0..15
    int y0   = seg * SEG;
    int x    = xs * XSTRIP + threadIdx.x;

    const float* __restrict__ pxx = g_sxx + (size_t)b * HW;
    const float* __restrict__ pyy = g_syy + (size_t)b * HW;
    const float* __restrict__ pxy = g_sxy + (size_t)b * HW;

    float axx = 0.f, ayy = 0.f, axy = 0.f;

    // Warm-up: accumulate rows [y0-5, y0+4] (zero padding for y<0)
    for (int y = y0 - KRAD; y <= y0 + KRAD - 1; y++) {
        if (y >= 0 && y < H) {
            int o = y * W + x;
            axx += pxx[o]; ayy += pyy[o]; axy += pxy[o];
        }
    }

    float csum = 0.f;
    for (int yy = y0; yy < y0 + SEG; yy++) {
        int ya = yy + KRAD;
        if (ya < H) {
            int o = ya * W + x;
            axx += pxx[o]; ayy += pyy[o]; axy += pxy[o];
        }
        // window now covers [yy-5, yy+5] (zero-padded)
        float cosv = axy / (sqrtf(axx) * sqrtf(ayy) + EPS_LCS);
        csum += cosv;
        int yr = yy - KRAD;
        if (yr >= 0) {
            int o = yr * W + x;
            axx -= pxx[o]; ayy -= pyy[o]; axy -= pxy[o];
        }
    }

    // block reduce csum
    __shared__ float red[XSTRIP];
    red[threadIdx.x] = csum;
    __syncthreads();
    for (int s = XSTRIP / 2; s > 0; s >>= 1) {
        if (threadIdx.x < s) red[threadIdx.x] += red[threadIdx.x + s];
        __syncthreads();
    }
    if (threadIdx.x == 0) atomicAdd(&g_cos_sum, red[0]);
}

// ---------------------------------------------------------------------------
// Finalize: PSNR from per-batch MSE, LCS from cos sum
// ---------------------------------------------------------------------------
__global__ void k_finalize(float* __restrict__ out) {
    const float scale = 10.0f / logf(10.0f);
    float s = 0.f;
#pragma unroll
    for (int b = 0; b < BATCH; b++) {
        float mse = g_mse[b] * (1.0f / (float)(CH * HW));
        s += logf(mse + EPS_PSNR);
    }
    float psnr_loss = scale * (s * (1.0f / (float)BATCH));
    float lcs_loss  = 1.0f - g_cos_sum * (1.0f / (float)(BATCH * HW));
    out[0] = psnr_loss + lcs_loss;
}

// ---------------------------------------------------------------------------
extern "C" void kernel_launch(void* const* d_in, const int* in_sizes, int n_in,
                              void* d_out, int out_size) {
    const float* pred = (const float*)d_in[0];
    const float* tgt  = (const float*)d_in[1];
    float* out = (float*)d_out;

    k_zero<<<1, 32>>>();
    k_prod_hsum<<<BATCH * H, W>>>(pred, tgt);
    k_vsum_cos<<<BATCH * (W / XSTRIP) * NSEG, XSTRIP>>>();
    k_finalize<<<1, 1>>>(out);
}